// round 3
// baseline (speedup 1.0000x reference)
#include <cuda_runtime.h>
#include <math.h>

// Problem constants (fixed shapes)
#define NN 20000
#define EE 320000
#define CC 64

// ---------------- scratch (device globals; no allocation allowed) ----------------
__device__ __align__(16) float g_s[NN * CC];            // up-projected scalars  s[n][c]
__device__ __align__(16) float g_v[NN * CC * 3];        // up-projected vectors  v[n][c][m]
__device__ __align__(16) float g_skip_s[NN * 2 * CC];   // skip_s[n][o], o<128
__device__ __align__(16) float g_skip_v[NN * CC * 3];   // skip_v[n][o][m]
__device__ __align__(16) float g_agg_s[NN * 2 * CC];    // agg_s[n][j], j<128 (raw sums)
__device__ __align__(16) float g_agg_v[NN * 3 * 2 * CC];// agg_v[n][m][c2], c2<128 (raw sums)

__device__ __forceinline__ float swishf(float x) { return x / (1.0f + __expf(-x)); }

__device__ __forceinline__ void red4(float* p, float a, float b, float c, float d) {
    asm volatile("red.global.add.v4.f32 [%0], {%1,%2,%3,%4};"
                 :: "l"(p), "f"(a), "f"(b), "f"(c), "f"(d) : "memory");
}

// ---- packed f32x2 helpers (Blackwell FFMA2 path) ----
__device__ __forceinline__ unsigned long long pack2(float lo, float hi) {
    unsigned long long r;
    asm("mov.b64 %0, {%1,%2};" : "=l"(r) : "f"(lo), "f"(hi));
    return r;
}
__device__ __forceinline__ unsigned long long ffma2(unsigned long long a,
                                                    unsigned long long b,
                                                    unsigned long long c) {
    unsigned long long d;
    asm("fma.rn.f32x2 %0, %1, %2, %3;" : "=l"(d) : "l"(a), "l"(b), "l"(c));
    return d;
}
__device__ __forceinline__ float2 unpack2(unsigned long long v) {
    float2 f;
    asm("mov.b64 {%0,%1}, %2;" : "=f"(f.x), "=f"(f.y) : "l"(v));
    return f;
}

// ---------------- kernel: zero aggregation buffers ----------------
__global__ void k_zero() {
    float4 z = make_float4(0.f, 0.f, 0.f, 0.f);
    int n1 = NN * 2 * CC / 4;
    for (int i = blockIdx.x * blockDim.x + threadIdx.x; i < n1; i += gridDim.x * blockDim.x)
        reinterpret_cast<float4*>(g_agg_s)[i] = z;
    int n2 = NN * 6 * CC / 4;
    for (int i = blockIdx.x * blockDim.x + threadIdx.x; i < n2; i += gridDim.x * blockDim.x)
        reinterpret_cast<float4*>(g_agg_v)[i] = z;
}

// ---------------- kernel: node up-projection ----------------
__global__ void __launch_bounds__(256) k_up(const float* __restrict__ scal,
                                            const float* __restrict__ nvec,
                                            const float* __restrict__ Wus,
                                            const float* __restrict__ Wuv) {
    extern __shared__ float sm[];
    float* sWs = sm;          // 64*64
    float* sWv = sm + 4096;   // 64*64
    float* sBuf = sm + 8192;  // 8 warps * 256
    int tid = threadIdx.x, wid = tid >> 5, l = tid & 31;
    for (int i = tid; i < 4096; i += 256) { sWs[i] = Wus[i]; sWv[i] = Wuv[i]; }
    __syncthreads();
    float* sc = sBuf + wid * 256;  // 64 scalars
    float* vb = sc + 64;           // 192 vector components [k*3+m]
    int nwarp = gridDim.x * 8;
    for (int n = blockIdx.x * 8 + wid; n < NN; n += nwarp) {
        sc[l] = scal[n * 64 + l];
        sc[l + 32] = scal[n * 64 + l + 32];
#pragma unroll
        for (int q = 0; q < 6; q++) vb[l + q * 32] = nvec[n * 192 + l + q * 32];
        __syncwarp();
        float a0 = 0.f, a1 = 0.f;
#pragma unroll
        for (int k = 0; k < 64; k++) {
            float a = sc[k];
            a0 = fmaf(a, sWs[k * 64 + l], a0);
            a1 = fmaf(a, sWs[k * 64 + l + 32], a1);
        }
        g_s[n * 64 + l] = a0;
        g_s[n * 64 + l + 32] = a1;
        float v0[3] = {0.f, 0.f, 0.f}, v1[3] = {0.f, 0.f, 0.f};
#pragma unroll
        for (int k = 0; k < 64; k++) {
            float w0 = sWv[k * 64 + l], w1 = sWv[k * 64 + l + 32];
#pragma unroll
            for (int m = 0; m < 3; m++) {
                float a = vb[k * 3 + m];
                v0[m] = fmaf(a, w0, v0[m]);
                v1[m] = fmaf(a, w1, v1[m]);
            }
        }
#pragma unroll
        for (int m = 0; m < 3; m++) {
            g_v[n * 192 + l * 3 + m] = v0[m];
            g_v[n * 192 + (l + 32) * 3 + m] = v1[m];
        }
        __syncwarp();
    }
}

// ---------------- kernel: per-species skip projections ----------------
__global__ void __launch_bounds__(256) k_skip(const float* __restrict__ scal,
                                              const float* __restrict__ nvec,
                                              const int* __restrict__ specie,
                                              const float* __restrict__ Wss,
                                              const float* __restrict__ Wsv) {
    extern __shared__ float sm[];
    float* sS = sm;            // 4*64*128 = 32768
    float* sV = sm + 32768;    // 4*64*64  = 16384
    float* sBuf = sm + 49152;  // 8 * 256
    int tid = threadIdx.x, wid = tid >> 5, l = tid & 31;
    for (int i = tid; i < 32768; i += 256) sS[i] = Wss[i];
    for (int i = tid; i < 16384; i += 256) sV[i] = Wsv[i];
    __syncthreads();
    float* sc = sBuf + wid * 256;
    float* vb = sc + 64;
    int nwarp = gridDim.x * 8;
    for (int n = blockIdx.x * 8 + wid; n < NN; n += nwarp) {
        sc[l] = scal[n * 64 + l];
        sc[l + 32] = scal[n * 64 + l + 32];
#pragma unroll
        for (int q = 0; q < 6; q++) vb[l + q * 32] = nvec[n * 192 + l + q * 32];
        __syncwarp();
        int sp = specie[n];
        const float* ws = sS + sp * 8192;
        const float* wv = sV + sp * 4096;
        float a0 = 0.f, a1 = 0.f, a2 = 0.f, a3 = 0.f;
#pragma unroll
        for (int k = 0; k < 64; k++) {
            float x = sc[k];
            const float* w = ws + k * 128;
            a0 = fmaf(x, w[l], a0);
            a1 = fmaf(x, w[l + 32], a1);
            a2 = fmaf(x, w[l + 64], a2);
            a3 = fmaf(x, w[l + 96], a3);
        }
        g_skip_s[n * 128 + l] = a0;
        g_skip_s[n * 128 + l + 32] = a1;
        g_skip_s[n * 128 + l + 64] = a2;
        g_skip_s[n * 128 + l + 96] = a3;
        float v0[3] = {0.f, 0.f, 0.f}, v1[3] = {0.f, 0.f, 0.f};
#pragma unroll
        for (int k = 0; k < 64; k++) {
            float w0 = wv[k * 64 + l], w1 = wv[k * 64 + l + 32];
#pragma unroll
            for (int m = 0; m < 3; m++) {
                float a = vb[k * 3 + m];
                v0[m] = fmaf(a, w0, v0[m]);
                v1[m] = fmaf(a, w1, v1[m]);
            }
        }
#pragma unroll
        for (int m = 0; m < 3; m++) {
            g_skip_v[n * 192 + l * 3 + m] = v0[m];
            g_skip_v[n * 192 + (l + 32) * 3 + m] = v1[m];
        }
        __syncwarp();
    }
}

// ---------------- kernel: edges (features -> MLP -> messages -> scatter) ----------------
// 128-edge tiles, 512 threads. Activations stored transposed [k][e] (pad 132) so the
// GEMM k-loops read edge-contiguous vectors; accumulators are f32x2 edge pairs (FFMA2).
// thread mapping: og = tid>>4 (0..31 = output group of 8 cols), eg = tid&15 (8 edges each).
#define EPAD 132

// smem float offsets
#define F_W1D 0          // dup-packed W1: 4096 u64 (8192 floats)
#define F_W2  8192       // 16384
#define F_W0  24576      // 512
#define F_H0  25088      // 64*132 = 8448
#define F_H1  33536      // 8448
#define F_FT  41984      // 8*132 = 1056
#define F_YB  43040      // 128*4 = 512
#define F_IDX 43552      // 256 ints
#define EDGE_SMEM_FLOATS 43808

__global__ void __launch_bounds__(512, 1) k_edge(const float* __restrict__ vectors,
                                                 const int* __restrict__ senders,
                                                 const int* __restrict__ receivers,
                                                 const float* __restrict__ W0,
                                                 const float* __restrict__ W1,
                                                 const float* __restrict__ W2) {
    extern __shared__ float sm[];
    unsigned long long* sW1d = reinterpret_cast<unsigned long long*>(sm + F_W1D); // [k*64+o] dup
    float* sW2 = sm + F_W2;
    float* sW0 = sm + F_W0;
    float* sH0 = sm + F_H0;   // [k][e] transposed
    float* sH1 = sm + F_H1;   // [k][e] transposed
    float* sFT = sm + F_FT;   // [b][e] transposed
    float* sYb = sm + F_YB;
    int* sSend = (int*)(sm + F_IDX);
    int* sRecv = sSend + 128;

    int tid = threadIdx.x;
    for (int i = tid; i < 512; i += 512) sW0[i] = W0[i];
    for (int i = tid; i < 4096; i += 512) {
        float w = W1[i];
        sW1d[i] = pack2(w, w);
    }
    for (int i = tid; i < 16384; i += 512) sW2[i] = W2[i];
    __syncthreads();

    const int og = tid >> 4;  // 0..31
    const int eg = tid & 15;  // 0..15
    const float SQRT2 = 1.41421356237309515f;
    const float SQRT3 = 1.73205080756887729f;
    const float INV_SQRT3 = 0.57735026918962576f;
    const float PI = 3.14159265358979323846f;

    int ntile = EE / 128;
    for (int t = blockIdx.x; t < ntile; t += gridDim.x) {
        int e0 = t * 128;
        // ---- phase 1: per-edge features (threads 0..127) ----
        if (tid < 128) {
            int e = e0 + tid;
            float vx = vectors[e * 3 + 0];
            float vy = vectors[e * 3 + 1];
            float vz = vectors[e * 3 + 2];
            float x = sqrtf(vx * vx + vy * vy + vz * vz);
            float sx = (x == 0.f) ? 1.f : x;
            float inv = 1.f / sx;
            sYb[tid * 4 + 0] = SQRT3 * vx * inv;
            sYb[tid * 4 + 1] = SQRT3 * vy * inv;
            sYb[tid * 4 + 2] = SQRT3 * vz * inv;
            float u = fminf(x, 1.f);
            float u2 = u * u, u3 = u2 * u, u6 = u3 * u3, u7 = u6 * u, u8 = u7 * u;
            float env = (x < 1.f) ? (1.f - 28.f * u6 + 48.f * u7 - 21.f * u8) : 0.f;
            float s1, c1;
            sincosf(PI * x, &s1, &c1);
            float pref = SQRT2 * inv * env;
            float sn = s1, cn = c1;
            sFT[0 * EPAD + tid] = pref * sn;
#pragma unroll
            for (int b = 1; b < 8; b++) {
                float sn1 = sn * c1 + cn * s1;
                float cn1 = cn * c1 - sn * s1;
                sn = sn1; cn = cn1;
                sFT[b * EPAD + tid] = pref * sn;
            }
            sSend[tid] = senders[e];
            sRecv[tid] = receivers[e];
        }
        __syncthreads();

        // ---- phase 2: h0 = swish(feat @ W0)  outputs o = og, og+32; edges eg*8..+7 ----
        {
            unsigned long long acc[4][2];
#pragma unroll
            for (int p = 0; p < 4; p++) { acc[p][0] = 0ULL; acc[p][1] = 0ULL; }
#pragma unroll
            for (int b = 0; b < 8; b++) {
                const ulonglong2* ap = reinterpret_cast<const ulonglong2*>(sFT + b * EPAD + eg * 8);
                ulonglong2 av0 = ap[0], av1 = ap[1];
                float w0 = sW0[b * 64 + og];
                float w1 = sW0[b * 64 + og + 32];
                unsigned long long w0d = pack2(w0, w0);
                unsigned long long w1d = pack2(w1, w1);
                acc[0][0] = ffma2(av0.x, w0d, acc[0][0]);
                acc[1][0] = ffma2(av0.y, w0d, acc[1][0]);
                acc[2][0] = ffma2(av1.x, w0d, acc[2][0]);
                acc[3][0] = ffma2(av1.y, w0d, acc[3][0]);
                acc[0][1] = ffma2(av0.x, w1d, acc[0][1]);
                acc[1][1] = ffma2(av0.y, w1d, acc[1][1]);
                acc[2][1] = ffma2(av1.x, w1d, acc[2][1]);
                acc[3][1] = ffma2(av1.y, w1d, acc[3][1]);
            }
#pragma unroll
            for (int o = 0; o < 2; o++) {
                float4 r0, r1;
                float2 f;
                f = unpack2(acc[0][o]); r0.x = swishf(f.x); r0.y = swishf(f.y);
                f = unpack2(acc[1][o]); r0.z = swishf(f.x); r0.w = swishf(f.y);
                f = unpack2(acc[2][o]); r1.x = swishf(f.x); r1.y = swishf(f.y);
                f = unpack2(acc[3][o]); r1.z = swishf(f.x); r1.w = swishf(f.y);
                float* dst = sH0 + (og + o * 32) * EPAD + eg * 8;
                *reinterpret_cast<float4*>(dst) = r0;
                *reinterpret_cast<float4*>(dst + 4) = r1;
            }
        }
        __syncthreads();

        // ---- phase 3: h1 = swish(h0 @ W1) ----
        {
            unsigned long long acc[4][2];
#pragma unroll
            for (int p = 0; p < 4; p++) { acc[p][0] = 0ULL; acc[p][1] = 0ULL; }
#pragma unroll 4
            for (int k = 0; k < 64; k++) {
                const ulonglong2* ap = reinterpret_cast<const ulonglong2*>(sH0 + k * EPAD + eg * 8);
                ulonglong2 av0 = ap[0], av1 = ap[1];
                unsigned long long w0d = sW1d[k * 64 + og];
                unsigned long long w1d = sW1d[k * 64 + og + 32];
                acc[0][0] = ffma2(av0.x, w0d, acc[0][0]);
                acc[1][0] = ffma2(av0.y, w0d, acc[1][0]);
                acc[2][0] = ffma2(av1.x, w0d, acc[2][0]);
                acc[3][0] = ffma2(av1.y, w0d, acc[3][0]);
                acc[0][1] = ffma2(av0.x, w1d, acc[0][1]);
                acc[1][1] = ffma2(av0.y, w1d, acc[1][1]);
                acc[2][1] = ffma2(av1.x, w1d, acc[2][1]);
                acc[3][1] = ffma2(av1.y, w1d, acc[3][1]);
            }
#pragma unroll
            for (int o = 0; o < 2; o++) {
                float4 r0, r1;
                float2 f;
                f = unpack2(acc[0][o]); r0.x = swishf(f.x); r0.y = swishf(f.y);
                f = unpack2(acc[1][o]); r0.z = swishf(f.x); r0.w = swishf(f.y);
                f = unpack2(acc[2][o]); r1.x = swishf(f.x); r1.y = swishf(f.y);
                f = unpack2(acc[3][o]); r1.z = swishf(f.x); r1.w = swishf(f.y);
                float* dst = sH1 + (og + o * 32) * EPAD + eg * 8;
                *reinterpret_cast<float4*>(dst) = r0;
                *reinterpret_cast<float4*>(dst + 4) = r1;
            }
        }
        __syncthreads();

        // ---- phase 4: mix = h1 @ W2, f32x2 edge-pair accumulators ----
        unsigned long long accp[4][8];
#pragma unroll
        for (int p = 0; p < 4; p++)
#pragma unroll
            for (int q = 0; q < 8; q++) accp[p][q] = 0ULL;
        {
            const int j0 = og * 8;
#pragma unroll 2
            for (int k = 0; k < 64; k++) {
                const ulonglong2* ap = reinterpret_cast<const ulonglong2*>(sH1 + k * EPAD + eg * 8);
                ulonglong2 av0 = ap[0], av1 = ap[1];
                float4 b0 = *reinterpret_cast<const float4*>(sW2 + k * 256 + j0);
                float4 b1 = *reinterpret_cast<const float4*>(sW2 + k * 256 + j0 + 4);
                unsigned long long bd[8];
                bd[0] = pack2(b0.x, b0.x); bd[1] = pack2(b0.y, b0.y);
                bd[2] = pack2(b0.z, b0.z); bd[3] = pack2(b0.w, b0.w);
                bd[4] = pack2(b1.x, b1.x); bd[5] = pack2(b1.y, b1.y);
                bd[6] = pack2(b1.z, b1.z); bd[7] = pack2(b1.w, b1.w);
#pragma unroll
                for (int q = 0; q < 8; q++) {
                    accp[0][q] = ffma2(av0.x, bd[q], accp[0][q]);
                    accp[1][q] = ffma2(av0.y, bd[q], accp[1][q]);
                    accp[2][q] = ffma2(av1.x, bd[q], accp[2][q]);
                    accp[3][q] = ffma2(av1.y, bd[q], accp[3][q]);
                }
            }
        }

        // ---- phase 5: messages + vectored scatter-add ----
        {
            const int r = og >> 3;
            const int c0 = (og & 7) * 8;
#pragma unroll 1
            for (int p = 0; p < 4; p++) {
                float mxs[2][8];
#pragma unroll
                for (int q = 0; q < 8; q++) {
                    float2 f = unpack2(accp[p][q]);
                    mxs[0][q] = f.x;
                    mxs[1][q] = f.y;
                }
#pragma unroll 1
                for (int sub = 0; sub < 2; sub++) {
                    int e = eg * 8 + p * 2 + sub;
                    int snd = sSend[e];
                    int rcv = sRecv[e];
                    const float* mx = mxs[sub];
                    if (r == 0) {
                        const float4* sp = reinterpret_cast<const float4*>(g_s + snd * 64 + c0);
                        float4 m0 = sp[0], m1 = sp[1];
                        red4(g_agg_s + rcv * 128 + c0,
                             m0.x * mx[0], m0.y * mx[1], m0.z * mx[2], m0.w * mx[3]);
                        red4(g_agg_s + rcv * 128 + c0 + 4,
                             m1.x * mx[4], m1.y * mx[5], m1.z * mx[6], m1.w * mx[7]);
                    } else if (r == 1) {
                        float y0 = sYb[e * 4 + 0], y1 = sYb[e * 4 + 1], y2 = sYb[e * 4 + 2];
                        const float4* vp = reinterpret_cast<const float4*>(g_v + snd * 192 + c0 * 3);
                        float mv[24];
#pragma unroll
                        for (int q = 0; q < 6; q++) {
                            float4 f = vp[q];
                            mv[q * 4 + 0] = f.x; mv[q * 4 + 1] = f.y;
                            mv[q * 4 + 2] = f.z; mv[q * 4 + 3] = f.w;
                        }
                        float tq[8];
#pragma unroll
                        for (int q = 0; q < 8; q++)
                            tq[q] = (mv[q * 3] * y0 + mv[q * 3 + 1] * y1 + mv[q * 3 + 2] * y2) * INV_SQRT3 * mx[q];
                        red4(g_agg_s + rcv * 128 + 64 + c0, tq[0], tq[1], tq[2], tq[3]);
                        red4(g_agg_s + rcv * 128 + 64 + c0 + 4, tq[4], tq[5], tq[6], tq[7]);
                    } else if (r == 2) {
                        const float4* vp = reinterpret_cast<const float4*>(g_v + snd * 192 + c0 * 3);
                        float mv[24];
#pragma unroll
                        for (int q = 0; q < 6; q++) {
                            float4 f = vp[q];
                            mv[q * 4 + 0] = f.x; mv[q * 4 + 1] = f.y;
                            mv[q * 4 + 2] = f.z; mv[q * 4 + 3] = f.w;
                        }
#pragma unroll
                        for (int m = 0; m < 3; m++) {
                            red4(g_agg_v + rcv * 384 + m * 128 + c0,
                                 mv[0 * 3 + m] * mx[0], mv[1 * 3 + m] * mx[1],
                                 mv[2 * 3 + m] * mx[2], mv[3 * 3 + m] * mx[3]);
                            red4(g_agg_v + rcv * 384 + m * 128 + c0 + 4,
                                 mv[4 * 3 + m] * mx[4], mv[5 * 3 + m] * mx[5],
                                 mv[6 * 3 + m] * mx[6], mv[7 * 3 + m] * mx[7]);
                        }
                    } else {
                        float y[3] = {sYb[e * 4 + 0], sYb[e * 4 + 1], sYb[e * 4 + 2]};
                        const float4* sp = reinterpret_cast<const float4*>(g_s + snd * 64 + c0);
                        float4 m0 = sp[0], m1 = sp[1];
                        float msv[8] = {m0.x * mx[0], m0.y * mx[1], m0.z * mx[2], m0.w * mx[3],
                                        m1.x * mx[4], m1.y * mx[5], m1.z * mx[6], m1.w * mx[7]};
#pragma unroll
                        for (int m = 0; m < 3; m++) {
                            red4(g_agg_v + rcv * 384 + m * 128 + 64 + c0,
                                 msv[0] * y[m], msv[1] * y[m], msv[2] * y[m], msv[3] * y[m]);
                            red4(g_agg_v + rcv * 384 + m * 128 + 64 + c0 + 4,
                                 msv[4] * y[m], msv[5] * y[m], msv[6] * y[m], msv[7] * y[m]);
                        }
                    }
                }
            }
        }
        __syncthreads();  // protect sFT/sYb/sSend before next tile's phase 1
    }
}

// ---------------- kernel: final down-projection + skip + gating + output ----------------
__global__ void __launch_bounds__(256) k_final(const float* __restrict__ Wds,
                                               const float* __restrict__ Wdv,
                                               float* __restrict__ out) {
    extern __shared__ float sm[];
    float* sWs = sm;            // 128*128 = 16384
    float* sWv = sm + 16384;    // 128*64  = 8192
    float* sBuf = sm + 24576;   // 8 * 520
    int tid = threadIdx.x, wid = tid >> 5, l = tid & 31;
    for (int i = tid; i < 16384; i += 256) sWs[i] = Wds[i];
    for (int i = tid; i < 8192; i += 256) sWv[i] = Wdv[i];
    __syncthreads();
    float* As = sBuf + wid * 520;  // 128: agg_s
    float* Av = As + 128;          // 384: agg_v [m][128]
    const float INV = 0.25f;       // 1/sqrt(16)
    int nwarp = gridDim.x * 8;
    for (int n = blockIdx.x * 8 + wid; n < NN; n += nwarp) {
#pragma unroll
        for (int q = 0; q < 4; q++) As[l + 32 * q] = g_agg_s[n * 128 + l + 32 * q];
#pragma unroll
        for (int q = 0; q < 12; q++) Av[l + 32 * q] = g_agg_v[n * 384 + l + 32 * q];
        __syncwarp();
        float a0 = 0.f, a1 = 0.f, a2 = 0.f, a3 = 0.f;
#pragma unroll 4
        for (int k = 0; k < 128; k++) {
            float x = As[k];
            const float* w = sWs + k * 128;
            a0 = fmaf(x, w[l], a0);
            a1 = fmaf(x, w[l + 32], a1);
            a2 = fmaf(x, w[l + 64], a2);
            a3 = fmaf(x, w[l + 96], a3);
        }
        float os0 = INV * a0 + g_skip_s[n * 128 + l];
        float os1 = INV * a1 + g_skip_s[n * 128 + l + 32];
        float os2 = INV * a2 + g_skip_s[n * 128 + l + 64];
        float os3 = INV * a3 + g_skip_s[n * 128 + l + 96];
        float scal0 = swishf(os0), scal1 = swishf(os1);
        float gate0 = swishf(os2), gate1 = swishf(os3);
        float v0[3] = {0.f, 0.f, 0.f}, v1[3] = {0.f, 0.f, 0.f};
#pragma unroll 4
        for (int k = 0; k < 128; k++) {
            float w0 = sWv[k * 64 + l], w1 = sWv[k * 64 + l + 32];
#pragma unroll
            for (int m = 0; m < 3; m++) {
                float a = Av[m * 128 + k];
                v0[m] = fmaf(a, w0, v0[m]);
                v1[m] = fmaf(a, w1, v1[m]);
            }
        }
        out[n * 256 + l] = scal0;
        out[n * 256 + l + 32] = scal1;
#pragma unroll
        for (int m = 0; m < 3; m++) {
            float ov0 = INV * v0[m] + g_skip_v[n * 192 + l * 3 + m];
            float ov1 = INV * v1[m] + g_skip_v[n * 192 + (l + 32) * 3 + m];
            out[n * 256 + 64 + l * 3 + m] = ov0 * gate0;
            out[n * 256 + 64 + (l + 32) * 3 + m] = ov1 * gate1;
        }
        __syncwarp();
    }
}

// ---------------- launch ----------------
extern "C" void kernel_launch(void* const* d_in, const int* in_sizes, int n_in,
                              void* d_out, int out_size) {
    const float* vectors      = (const float*)d_in[0];
    const float* node_scalars = (const float*)d_in[1];
    const float* node_vectors = (const float*)d_in[2];
    const int*   node_specie  = (const int*)d_in[3];
    const int*   senders      = (const int*)d_in[4];
    const int*   receivers    = (const int*)d_in[5];
    const float* W_skip_s     = (const float*)d_in[6];
    const float* W_skip_v     = (const float*)d_in[7];
    const float* W_up_s       = (const float*)d_in[8];
    const float* W_up_v       = (const float*)d_in[9];
    const float* W_mlp0       = (const float*)d_in[10];
    const float* W_mlp1       = (const float*)d_in[11];
    const float* W_mlp2       = (const float*)d_in[12];
    const float* W_down_s     = (const float*)d_in[13];
    const float* W_down_v     = (const float*)d_in[14];
    float* out = (float*)d_out;

    const int UP_SMEM    = (8192 + 8 * 256) * 4;            // 40 KB
    const int SKIP_SMEM  = (49152 + 8 * 256) * 4;           // 200 KB
    const int EDGE_SMEM  = EDGE_SMEM_FLOATS * 4;            // ~171 KB
    const int FINAL_SMEM = (24576 + 8 * 520) * 4;           // ~114.5 KB

    cudaFuncSetAttribute(k_skip,  cudaFuncAttributeMaxDynamicSharedMemorySize, SKIP_SMEM);
    cudaFuncSetAttribute(k_edge,  cudaFuncAttributeMaxDynamicSharedMemorySize, EDGE_SMEM);
    cudaFuncSetAttribute(k_final, cudaFuncAttributeMaxDynamicSharedMemorySize, FINAL_SMEM);

    k_zero<<<2048, 256>>>();
    k_up<<<512, 256, UP_SMEM>>>(node_scalars, node_vectors, W_up_s, W_up_v);
    k_skip<<<296, 256, SKIP_SMEM>>>(node_scalars, node_vectors, node_specie, W_skip_s, W_skip_v);
    k_edge<<<148, 512, EDGE_SMEM>>>(vectors, senders, receivers, W_mlp0, W_mlp1, W_mlp2);
    k_final<<<296, 256, FINAL_SMEM>>>(W_down_s, W_down_v, out);
}

// round 4
// speedup vs baseline: 1.7309x; 1.7309x over previous
#include <cuda_runtime.h>
#include <math.h>

// Problem constants (fixed shapes)
#define NN 20000
#define EE 320000
#define CC 64

// ---------------- scratch (device globals; no allocation allowed) ----------------
__device__ __align__(16) float g_s[NN * CC];            // up-projected scalars  s[n][c]
__device__ __align__(16) float g_v[NN * CC * 3];        // up-projected vectors  v[n][c][m]
__device__ __align__(16) float g_skip_s[NN * 2 * CC];   // skip_s[n][o], o<128
__device__ __align__(16) float g_skip_v[NN * CC * 3];   // skip_v[n][o][m]
__device__ __align__(16) float g_agg_s[NN * 2 * CC];    // agg_s[n][j], j<128 (raw sums)
__device__ __align__(16) float g_agg_v[NN * 3 * 2 * CC];// agg_v[n][m][c2], c2<128 (raw sums)

__device__ __forceinline__ float swishf(float x) { return x / (1.0f + __expf(-x)); }

__device__ __forceinline__ void red4(float* p, float a, float b, float c, float d) {
    asm volatile("red.global.add.v4.f32 [%0], {%1,%2,%3,%4};"
                 :: "l"(p), "f"(a), "f"(b), "f"(c), "f"(d) : "memory");
}

// ---------------- kernel: zero aggregation buffers ----------------
__global__ void k_zero() {
    float4 z = make_float4(0.f, 0.f, 0.f, 0.f);
    int n1 = NN * 2 * CC / 4;
    for (int i = blockIdx.x * blockDim.x + threadIdx.x; i < n1; i += gridDim.x * blockDim.x)
        reinterpret_cast<float4*>(g_agg_s)[i] = z;
    int n2 = NN * 6 * CC / 4;
    for (int i = blockIdx.x * blockDim.x + threadIdx.x; i < n2; i += gridDim.x * blockDim.x)
        reinterpret_cast<float4*>(g_agg_v)[i] = z;
}

// ---------------- kernel: node up-projection ----------------
__global__ void __launch_bounds__(256) k_up(const float* __restrict__ scal,
                                            const float* __restrict__ nvec,
                                            const float* __restrict__ Wus,
                                            const float* __restrict__ Wuv) {
    extern __shared__ float sm[];
    float* sWs = sm;          // 64*64
    float* sWv = sm + 4096;   // 64*64
    float* sBuf = sm + 8192;  // 8 warps * 256
    int tid = threadIdx.x, wid = tid >> 5, l = tid & 31;
    for (int i = tid; i < 4096; i += 256) { sWs[i] = Wus[i]; sWv[i] = Wuv[i]; }
    __syncthreads();
    float* sc = sBuf + wid * 256;  // 64 scalars
    float* vb = sc + 64;           // 192 vector components [k*3+m]
    int nwarp = gridDim.x * 8;
    for (int n = blockIdx.x * 8 + wid; n < NN; n += nwarp) {
        sc[l] = scal[n * 64 + l];
        sc[l + 32] = scal[n * 64 + l + 32];
#pragma unroll
        for (int q = 0; q < 6; q++) vb[l + q * 32] = nvec[n * 192 + l + q * 32];
        __syncwarp();
        float a0 = 0.f, a1 = 0.f;
#pragma unroll
        for (int k = 0; k < 64; k++) {
            float a = sc[k];
            a0 = fmaf(a, sWs[k * 64 + l], a0);
            a1 = fmaf(a, sWs[k * 64 + l + 32], a1);
        }
        g_s[n * 64 + l] = a0;
        g_s[n * 64 + l + 32] = a1;
        float v0[3] = {0.f, 0.f, 0.f}, v1[3] = {0.f, 0.f, 0.f};
#pragma unroll
        for (int k = 0; k < 64; k++) {
            float w0 = sWv[k * 64 + l], w1 = sWv[k * 64 + l + 32];
#pragma unroll
            for (int m = 0; m < 3; m++) {
                float a = vb[k * 3 + m];
                v0[m] = fmaf(a, w0, v0[m]);
                v1[m] = fmaf(a, w1, v1[m]);
            }
        }
#pragma unroll
        for (int m = 0; m < 3; m++) {
            g_v[n * 192 + l * 3 + m] = v0[m];
            g_v[n * 192 + (l + 32) * 3 + m] = v1[m];
        }
        __syncwarp();
    }
}

// ---------------- kernel: per-species skip projections ----------------
__global__ void __launch_bounds__(256) k_skip(const float* __restrict__ scal,
                                              const float* __restrict__ nvec,
                                              const int* __restrict__ specie,
                                              const float* __restrict__ Wss,
                                              const float* __restrict__ Wsv) {
    extern __shared__ float sm[];
    float* sS = sm;            // 4*64*128 = 32768
    float* sV = sm + 32768;    // 4*64*64  = 16384
    float* sBuf = sm + 49152;  // 8 * 256
    int tid = threadIdx.x, wid = tid >> 5, l = tid & 31;
    for (int i = tid; i < 32768; i += 256) sS[i] = Wss[i];
    for (int i = tid; i < 16384; i += 256) sV[i] = Wsv[i];
    __syncthreads();
    float* sc = sBuf + wid * 256;
    float* vb = sc + 64;
    int nwarp = gridDim.x * 8;
    for (int n = blockIdx.x * 8 + wid; n < NN; n += nwarp) {
        sc[l] = scal[n * 64 + l];
        sc[l + 32] = scal[n * 64 + l + 32];
#pragma unroll
        for (int q = 0; q < 6; q++) vb[l + q * 32] = nvec[n * 192 + l + q * 32];
        __syncwarp();
        int sp = specie[n];
        const float* ws = sS + sp * 8192;
        const float* wv = sV + sp * 4096;
        float a0 = 0.f, a1 = 0.f, a2 = 0.f, a3 = 0.f;
#pragma unroll
        for (int k = 0; k < 64; k++) {
            float x = sc[k];
            const float* w = ws + k * 128;
            a0 = fmaf(x, w[l], a0);
            a1 = fmaf(x, w[l + 32], a1);
            a2 = fmaf(x, w[l + 64], a2);
            a3 = fmaf(x, w[l + 96], a3);
        }
        g_skip_s[n * 128 + l] = a0;
        g_skip_s[n * 128 + l + 32] = a1;
        g_skip_s[n * 128 + l + 64] = a2;
        g_skip_s[n * 128 + l + 96] = a3;
        float v0[3] = {0.f, 0.f, 0.f}, v1[3] = {0.f, 0.f, 0.f};
#pragma unroll
        for (int k = 0; k < 64; k++) {
            float w0 = wv[k * 64 + l], w1 = wv[k * 64 + l + 32];
#pragma unroll
            for (int m = 0; m < 3; m++) {
                float a = vb[k * 3 + m];
                v0[m] = fmaf(a, w0, v0[m]);
                v1[m] = fmaf(a, w1, v1[m]);
            }
        }
#pragma unroll
        for (int m = 0; m < 3; m++) {
            g_skip_v[n * 192 + l * 3 + m] = v0[m];
            g_skip_v[n * 192 + (l + 32) * 3 + m] = v1[m];
        }
        __syncwarp();
    }
}

// ---------------- kernel: edges (features -> MLP -> messages -> scatter) ----------------
// 64-edge tiles; MLP weights in smem; 8e x 8o register tiles. In-place H buffer
// (phase-3 swish written back into sH0 after a sync) cuts smem to ~102KB so
// TWO blocks fit per SM (16 warps, 25% occ) with the proven R2 code structure.
// thread mapping: og = tid>>3 (0..31), eg = tid&7.
__global__ void __launch_bounds__(256, 2) k_edge(const float* __restrict__ vectors,
                                                 const int* __restrict__ senders,
                                                 const int* __restrict__ receivers,
                                                 const float* __restrict__ W0,
                                                 const float* __restrict__ W1,
                                                 const float* __restrict__ W2) {
    extern __shared__ float sm[];
    float* sW0 = sm;                 // 8*64   = 512
    float* sW1 = sm + 512;           // 64*64  = 4096
    float* sW2 = sm + 4608;          // 64*256 = 16384
    float* sH  = sm + 20992;         // 64*65  = 4160 (padded) — reused for H0 then H1
    float* sF  = sm + 25152;         // 64*9   = 576 (padded)
    float* sYb = sm + 25728;         // 64*4   = 256
    int* sSend = (int*)(sm + 25984); // 64
    int* sRecv = sSend + 64;         // 64  -> total 26112 floats = 104448 B

    int tid = threadIdx.x;
    for (int i = tid; i < 512; i += 256) sW0[i] = W0[i];
    for (int i = tid; i < 4096; i += 256) sW1[i] = W1[i];
    for (int i = tid; i < 16384; i += 256) sW2[i] = W2[i];
    __syncthreads();

    const int og = tid >> 3;  // 0..31
    const int eg = tid & 7;   // 0..7
    const float SQRT2 = 1.41421356237309515f;
    const float SQRT3 = 1.73205080756887729f;
    const float INV_SQRT3 = 0.57735026918962576f;
    const float PI = 3.14159265358979323846f;

    int ntile = EE / 64;
    for (int t = blockIdx.x; t < ntile; t += gridDim.x) {
        int e0 = t * 64;
        // ---- phase 1: per-edge features (threads 0..63) ----
        if (tid < 64) {
            int e = e0 + tid;
            float vx = vectors[e * 3 + 0];
            float vy = vectors[e * 3 + 1];
            float vz = vectors[e * 3 + 2];
            float x = sqrtf(vx * vx + vy * vy + vz * vz);
            float sx = (x == 0.f) ? 1.f : x;
            float inv = 1.f / sx;
            sYb[tid * 4 + 0] = SQRT3 * vx * inv;
            sYb[tid * 4 + 1] = SQRT3 * vy * inv;
            sYb[tid * 4 + 2] = SQRT3 * vz * inv;
            float u = fminf(x, 1.f);
            float u2 = u * u, u3 = u2 * u, u6 = u3 * u3, u7 = u6 * u, u8 = u7 * u;
            float env = (x < 1.f) ? (1.f - 28.f * u6 + 48.f * u7 - 21.f * u8) : 0.f;
            float s1, c1;
            sincosf(PI * x, &s1, &c1);
            float pref = SQRT2 * inv * env;
            float sn = s1, cn = c1;
            sF[tid * 9 + 0] = pref * sn;
#pragma unroll
            for (int b = 1; b < 8; b++) {
                float sn1 = sn * c1 + cn * s1;
                float cn1 = cn * c1 - sn * s1;
                sn = sn1; cn = cn1;
                sF[tid * 9 + b] = pref * sn;
            }
            sSend[tid] = senders[e];
            sRecv[tid] = receivers[e];
        }
        __syncthreads();

        // ---- phase 2: h0 = swish(feat @ W0)  [64x8]@[8x64] -> sH ----
        {
            float a0[8], a1[8];
#pragma unroll
            for (int i = 0; i < 8; i++) { a0[i] = 0.f; a1[i] = 0.f; }
#pragma unroll
            for (int b = 0; b < 8; b++) {
                float w0 = sW0[b * 64 + og];
                float w1 = sW0[b * 64 + og + 32];
#pragma unroll
                for (int i = 0; i < 8; i++) {
                    float f = sF[(eg * 8 + i) * 9 + b];
                    a0[i] = fmaf(f, w0, a0[i]);
                    a1[i] = fmaf(f, w1, a1[i]);
                }
            }
#pragma unroll
            for (int i = 0; i < 8; i++) {
                sH[(eg * 8 + i) * 65 + og] = swishf(a0[i]);
                sH[(eg * 8 + i) * 65 + og + 32] = swishf(a1[i]);
            }
        }
        __syncthreads();

        // ---- phase 3: h1 = swish(h0 @ W1), written back in place into sH ----
        {
            float a0[8], a1[8];
#pragma unroll
            for (int i = 0; i < 8; i++) { a0[i] = 0.f; a1[i] = 0.f; }
#pragma unroll 2
            for (int k = 0; k < 64; k++) {
                float w0 = sW1[k * 64 + og];
                float w1 = sW1[k * 64 + og + 32];
#pragma unroll
                for (int i = 0; i < 8; i++) {
                    float h = sH[(eg * 8 + i) * 65 + k];
                    a0[i] = fmaf(h, w0, a0[i]);
                    a1[i] = fmaf(h, w1, a1[i]);
                }
            }
            __syncthreads();  // everyone done READING h0 before in-place overwrite
#pragma unroll
            for (int i = 0; i < 8; i++) {
                sH[(eg * 8 + i) * 65 + og] = swishf(a0[i]);
                sH[(eg * 8 + i) * 65 + og + 32] = swishf(a1[i]);
            }
        }
        __syncthreads();

        // ---- phase 4: mix = h1 @ W2  [64x64]@[64x256], thread tile 8e x 8j ----
        float acc[8][8];
#pragma unroll
        for (int i = 0; i < 8; i++)
#pragma unroll
            for (int q = 0; q < 8; q++) acc[i][q] = 0.f;
        {
            const int j0 = og * 8;
#pragma unroll 2
            for (int k = 0; k < 64; k++) {
                float4 b0 = *reinterpret_cast<const float4*>(sW2 + k * 256 + j0);
                float4 b1 = *reinterpret_cast<const float4*>(sW2 + k * 256 + j0 + 4);
#pragma unroll
                for (int i = 0; i < 8; i++) {
                    float a = sH[(eg * 8 + i) * 65 + k];
                    acc[i][0] = fmaf(a, b0.x, acc[i][0]);
                    acc[i][1] = fmaf(a, b0.y, acc[i][1]);
                    acc[i][2] = fmaf(a, b0.z, acc[i][2]);
                    acc[i][3] = fmaf(a, b0.w, acc[i][3]);
                    acc[i][4] = fmaf(a, b1.x, acc[i][4]);
                    acc[i][5] = fmaf(a, b1.y, acc[i][5]);
                    acc[i][6] = fmaf(a, b1.z, acc[i][6]);
                    acc[i][7] = fmaf(a, b1.w, acc[i][7]);
                }
            }
        }

        // ---- phase 5: messages + vectored scatter-add ----
        {
            const int r = og >> 3;
            const int c0 = (og & 7) * 8;
#pragma unroll 1
            for (int i = 0; i < 8; i++) {
                int e = eg * 8 + i;
                int snd = sSend[e];
                int rcv = sRecv[e];
                float* mx = acc[i];
                if (r == 0) {
                    const float4* sp = reinterpret_cast<const float4*>(g_s + snd * 64 + c0);
                    float4 m0 = sp[0], m1 = sp[1];
                    red4(g_agg_s + rcv * 128 + c0,
                         m0.x * mx[0], m0.y * mx[1], m0.z * mx[2], m0.w * mx[3]);
                    red4(g_agg_s + rcv * 128 + c0 + 4,
                         m1.x * mx[4], m1.y * mx[5], m1.z * mx[6], m1.w * mx[7]);
                } else if (r == 1) {
                    float y0 = sYb[e * 4 + 0], y1 = sYb[e * 4 + 1], y2 = sYb[e * 4 + 2];
                    const float4* vp = reinterpret_cast<const float4*>(g_v + snd * 192 + c0 * 3);
                    float mv[24];
#pragma unroll
                    for (int q = 0; q < 6; q++) {
                        float4 f = vp[q];
                        mv[q * 4 + 0] = f.x; mv[q * 4 + 1] = f.y;
                        mv[q * 4 + 2] = f.z; mv[q * 4 + 3] = f.w;
                    }
                    float tq[8];
#pragma unroll
                    for (int q = 0; q < 8; q++)
                        tq[q] = (mv[q * 3] * y0 + mv[q * 3 + 1] * y1 + mv[q * 3 + 2] * y2) * INV_SQRT3 * mx[q];
                    red4(g_agg_s + rcv * 128 + 64 + c0, tq[0], tq[1], tq[2], tq[3]);
                    red4(g_agg_s + rcv * 128 + 64 + c0 + 4, tq[4], tq[5], tq[6], tq[7]);
                } else if (r == 2) {
                    const float4* vp = reinterpret_cast<const float4*>(g_v + snd * 192 + c0 * 3);
                    float mv[24];
#pragma unroll
                    for (int q = 0; q < 6; q++) {
                        float4 f = vp[q];
                        mv[q * 4 + 0] = f.x; mv[q * 4 + 1] = f.y;
                        mv[q * 4 + 2] = f.z; mv[q * 4 + 3] = f.w;
                    }
#pragma unroll
                    for (int m = 0; m < 3; m++) {
                        red4(g_agg_v + rcv * 384 + m * 128 + c0,
                             mv[0 * 3 + m] * mx[0], mv[1 * 3 + m] * mx[1],
                             mv[2 * 3 + m] * mx[2], mv[3 * 3 + m] * mx[3]);
                        red4(g_agg_v + rcv * 384 + m * 128 + c0 + 4,
                             mv[4 * 3 + m] * mx[4], mv[5 * 3 + m] * mx[5],
                             mv[6 * 3 + m] * mx[6], mv[7 * 3 + m] * mx[7]);
                    }
                } else {
                    float y[3] = {sYb[e * 4 + 0], sYb[e * 4 + 1], sYb[e * 4 + 2]};
                    const float4* sp = reinterpret_cast<const float4*>(g_s + snd * 64 + c0);
                    float4 m0 = sp[0], m1 = sp[1];
                    float msv[8] = {m0.x * mx[0], m0.y * mx[1], m0.z * mx[2], m0.w * mx[3],
                                    m1.x * mx[4], m1.y * mx[5], m1.z * mx[6], m1.w * mx[7]};
#pragma unroll
                    for (int m = 0; m < 3; m++) {
                        red4(g_agg_v + rcv * 384 + m * 128 + 64 + c0,
                             msv[0] * y[m], msv[1] * y[m], msv[2] * y[m], msv[3] * y[m]);
                        red4(g_agg_v + rcv * 384 + m * 128 + 64 + c0 + 4,
                             msv[4] * y[m], msv[5] * y[m], msv[6] * y[m], msv[7] * y[m]);
                    }
                }
            }
        }
        __syncthreads();  // protect sF/sYb/sSend/sH before next tile
    }
}

// ---------------- kernel: final down-projection + skip + gating + output ----------------
__global__ void __launch_bounds__(256) k_final(const float* __restrict__ Wds,
                                               const float* __restrict__ Wdv,
                                               float* __restrict__ out) {
    extern __shared__ float sm[];
    float* sWs = sm;            // 128*128 = 16384
    float* sWv = sm + 16384;    // 128*64  = 8192
    float* sBuf = sm + 24576;   // 8 * 520
    int tid = threadIdx.x, wid = tid >> 5, l = tid & 31;
    for (int i = tid; i < 16384; i += 256) sWs[i] = Wds[i];
    for (int i = tid; i < 8192; i += 256) sWv[i] = Wdv[i];
    __syncthreads();
    float* As = sBuf + wid * 520;  // 128: agg_s
    float* Av = As + 128;          // 384: agg_v [m][128]
    const float INV = 0.25f;       // 1/sqrt(16)
    int nwarp = gridDim.x * 8;
    for (int n = blockIdx.x * 8 + wid; n < NN; n += nwarp) {
#pragma unroll
        for (int q = 0; q < 4; q++) As[l + 32 * q] = g_agg_s[n * 128 + l + 32 * q];
#pragma unroll
        for (int q = 0; q < 12; q++) Av[l + 32 * q] = g_agg_v[n * 384 + l + 32 * q];
        __syncwarp();
        float a0 = 0.f, a1 = 0.f, a2 = 0.f, a3 = 0.f;
#pragma unroll 4
        for (int k = 0; k < 128; k++) {
            float x = As[k];
            const float* w = sWs + k * 128;
            a0 = fmaf(x, w[l], a0);
            a1 = fmaf(x, w[l + 32], a1);
            a2 = fmaf(x, w[l + 64], a2);
            a3 = fmaf(x, w[l + 96], a3);
        }
        float os0 = INV * a0 + g_skip_s[n * 128 + l];
        float os1 = INV * a1 + g_skip_s[n * 128 + l + 32];
        float os2 = INV * a2 + g_skip_s[n * 128 + l + 64];
        float os3 = INV * a3 + g_skip_s[n * 128 + l + 96];
        float scal0 = swishf(os0), scal1 = swishf(os1);
        float gate0 = swishf(os2), gate1 = swishf(os3);
        float v0[3] = {0.f, 0.f, 0.f}, v1[3] = {0.f, 0.f, 0.f};
#pragma unroll 4
        for (int k = 0; k < 128; k++) {
            float w0 = sWv[k * 64 + l], w1 = sWv[k * 64 + l + 32];
#pragma unroll
            for (int m = 0; m < 3; m++) {
                float a = Av[m * 128 + k];
                v0[m] = fmaf(a, w0, v0[m]);
                v1[m] = fmaf(a, w1, v1[m]);
            }
        }
        out[n * 256 + l] = scal0;
        out[n * 256 + l + 32] = scal1;
#pragma unroll
        for (int m = 0; m < 3; m++) {
            float ov0 = INV * v0[m] + g_skip_v[n * 192 + l * 3 + m];
            float ov1 = INV * v1[m] + g_skip_v[n * 192 + (l + 32) * 3 + m];
            out[n * 256 + 64 + l * 3 + m] = ov0 * gate0;
            out[n * 256 + 64 + (l + 32) * 3 + m] = ov1 * gate1;
        }
        __syncwarp();
    }
}

// ---------------- launch ----------------
extern "C" void kernel_launch(void* const* d_in, const int* in_sizes, int n_in,
                              void* d_out, int out_size) {
    const float* vectors      = (const float*)d_in[0];
    const float* node_scalars = (const float*)d_in[1];
    const float* node_vectors = (const float*)d_in[2];
    const int*   node_specie  = (const int*)d_in[3];
    const int*   senders      = (const int*)d_in[4];
    const int*   receivers    = (const int*)d_in[5];
    const float* W_skip_s     = (const float*)d_in[6];
    const float* W_skip_v     = (const float*)d_in[7];
    const float* W_up_s       = (const float*)d_in[8];
    const float* W_up_v       = (const float*)d_in[9];
    const float* W_mlp0       = (const float*)d_in[10];
    const float* W_mlp1       = (const float*)d_in[11];
    const float* W_mlp2       = (const float*)d_in[12];
    const float* W_down_s     = (const float*)d_in[13];
    const float* W_down_v     = (const float*)d_in[14];
    float* out = (float*)d_out;

    const int UP_SMEM    = (8192 + 8 * 256) * 4;            // 40 KB
    const int SKIP_SMEM  = (49152 + 8 * 256) * 4;           // 200 KB
    const int EDGE_SMEM  = 26112 * 4;                       // 102 KB -> 2 blocks/SM
    const int FINAL_SMEM = (24576 + 8 * 520) * 4;           // ~114.5 KB

    cudaFuncSetAttribute(k_skip,  cudaFuncAttributeMaxDynamicSharedMemorySize, SKIP_SMEM);
    cudaFuncSetAttribute(k_edge,  cudaFuncAttributeMaxDynamicSharedMemorySize, EDGE_SMEM);
    cudaFuncSetAttribute(k_final, cudaFuncAttributeMaxDynamicSharedMemorySize, FINAL_SMEM);

    k_zero<<<2048, 256>>>();
    k_up<<<512, 256, UP_SMEM>>>(node_scalars, node_vectors, W_up_s, W_up_v);
    k_skip<<<296, 256, SKIP_SMEM>>>(node_scalars, node_vectors, node_specie, W_skip_s, W_skip_v);
    k_edge<<<296, 256, EDGE_SMEM>>>(vectors, senders, receivers, W_mlp0, W_mlp1, W_mlp2);
    k_final<<<296, 256, FINAL_SMEM>>>(W_down_s, W_down_v, out);
}